// round 5
// baseline (speedup 1.0000x reference)
#include <cuda_runtime.h>

#define NB 4096
#define ND 32
#define NK 64
#define NHID 128
#define ALPHA 0.2f
#define NEGV (-9e15f)
#define OBSW 3584

// ---- gat_attn smem layout (floats) ----
#define OFF_ADJ   0        // 2048
#define OFF_DOCKT 2048     // 16*68
#define DKTLD 68
#define OFF_DRONE 3136     // 512
#define OFF_CT    3648     // 16*132
#define CTLD 132
#define OFF_SCR   5760     // 4096
#define OFF_ATTN  9856     // 512
#define OFF_SRC   10368    // 128
#define OFF_DST   10496    // 256
#define OFF_VS    10752    // 64
#define OFF_VD    10816    // 64
#define OFF_U     10880    // 128
#define SMF2      11008    // 44032 B

// ---- logits smem (floats) ----
#define L_ADJ 0            // 2048
#define L_R   2048         // 128*36
#define L_RLD 36
#define L_HK  6656         // 128*68
#define L_HLD 68
#define L_T   15360        // 32
#define L_SMF 15392        // 61568 B

// ---- critic smem (floats) ----
#define C_HLD 68
#define C_SW  17408        // shd 256*68
#define C_SMF 21760        // 87040 B

__device__ float g_hdT[(size_t)NB * NHID * ND];     // [b][a][n] 64 MB
__device__ float g_hkT[(size_t)NB * NHID * NK];     // [b][k][m] 128 MB
__device__ float g_rT[(size_t)NB * NHID * ND];      // [b][j][n] 64 MB
__device__ float g_t[NB * ND];
__device__ float g_hpart[8ull * NB * 64];
__device__ float g_Wc1p[4096 * 64];
__device__ float g_M[NHID * NHID];
__device__ float g_vb[NHID];
__device__ float g_u[NHID];
__device__ float g_s0[1];
__device__ float g_vsrc[64];
__device__ float g_vdst[64];
__device__ float g_wbar[16 * NHID];

__device__ __forceinline__ float eluf(float x) { return x > 0.f ? x : expm1f(x); }

// ================= precompute =================
__global__ void precomp(const float* __restrict__ Wdr, const float* __restrict__ Wdk,
                        const float* __restrict__ asrc, const float* __restrict__ adst,
                        const float* __restrict__ Wad, const float* __restrict__ Wak,
                        const float* __restrict__ bad, const float* __restrict__ bak)
{
    const int t = threadIdx.x;
    if (blockIdx.x < 16) {
        __shared__ float swad[8 * 128];
        __shared__ float swak[32 * 128];
        const int a0 = blockIdx.x * 8;
        for (int i = t; i < 1024; i += 256) swad[i] = Wad[a0 * 128 + i];
        for (int jb = 0; jb < 4; jb++) {
            __syncthreads();
            for (int i = t; i < 4096; i += 256) swak[i] = Wak[jb * 4096 + i];
            __syncthreads();
            const int aa = t >> 5, jl = t & 31;
            float s = 0.f;
            for (int c = 0; c < 128; c++) {
                int cc = (c + jl) & 127;
                s += swad[aa * 128 + cc] * swak[jl * 128 + cc];
            }
            g_M[(a0 + aa) * 128 + jb * 32 + jl] = s;
        }
        if (t < 8) {
            float s = 0.f;
            for (int c = 0; c < 128; c++) s += swad[t * 128 + c] * bak[c];
            g_u[a0 + t] = s;
        }
    } else {
        __shared__ float sb[128];
        if (t < 128) sb[t] = bad[t];
        __syncthreads();
        if (t < 128) {
            float s = 0.f;
            for (int c = 0; c < 128; c++) s += sb[c] * Wak[t * 128 + c];
            g_vb[t] = s;
        }
        if (t == 0) {
            float s = 0.f;
            for (int c = 0; c < 128; c++) s += sb[c] * bak[c];
            g_s0[0] = s;
        }
        if (t < 64) {
            int h = t >> 4, f = t & 15;
            float s = 0.f;
            for (int c = 0; c < 128; c++) s += Wdr[(h * 16 + f) * 128 + c] * asrc[h * 128 + c];
            g_vsrc[t] = s;
        } else if (t < 128) {
            int u2 = t - 64, h = u2 >> 4, f = u2 & 15;
            float s = 0.f;
            for (int c = 0; c < 128; c++) s += Wdk[(h * 16 + f) * 128 + c] * adst[h * 128 + c];
            g_vdst[u2] = s;
        }
        for (int i = t; i < 2048; i += 256) {
            float s = Wdk[i] + Wdk[2048 + i] + Wdk[4096 + i] + Wdk[6144 + i];
            g_wbar[i] = s * 0.25f;
        }
    }
}

__global__ void permute_wc1(const float* __restrict__ Wc1)
{
    int e0 = blockIdx.x * 16384;
    for (int i = threadIdx.x; i < 16384; i += 256) {
        int e = e0 + i;
        int row = e >> 6, j = e & 63;
        int n = row & 31, a = row >> 5;          // k' = a*32+n
        g_Wc1p[e] = Wc1[(n * 128 + a) * 64 + j];
    }
}

// ================= per-batch attention + h kernels =================
__global__ void __launch_bounds__(256, 3) gat_attn(
    const float* __restrict__ obs, const float* __restrict__ Wdk)
{
    extern __shared__ float sm[];
    const int b = blockIdx.x, t = threadIdx.x;
    const int w = t >> 5, lane = t & 31;
    const int k4 = lane * 4;
    const float* rowp = obs + (size_t)b * OBSW;

    for (int i = t; i < 512;  i += 256) sm[OFF_DRONE + i] = rowp[i];
    for (int i = t; i < 1024; i += 256) {
        int m = i >> 4, f = i & 15;
        sm[OFF_DOCKT + f * DKTLD + m] = rowp[512 + i];
    }
    for (int i = t; i < 2048; i += 256) sm[OFF_ADJ + i] = rowp[1536 + i];
    if (t < 64)       sm[OFF_VS + t]      = g_vsrc[t];
    else if (t < 128) sm[OFF_VD + t - 64] = g_vdst[t - 64];
    else if (t < 256) sm[OFF_U + t - 128] = g_u[t - 128];
    __syncthreads();

    if (t < 128) {
        int h = t >> 5, n = t & 31;
        float s = 0.f;
        #pragma unroll
        for (int f = 0; f < 16; f++) s += sm[OFF_DRONE + n * 16 + f] * sm[OFF_VS + h * 16 + f];
        sm[OFF_SRC + t] = s;
    }
    {
        int h = t >> 6, m = t & 63;
        float s = 0.f;
        #pragma unroll
        for (int f = 0; f < 16; f++) s += sm[OFF_DOCKT + f * DKTLD + m] * sm[OFF_VD + h * 16 + f];
        sm[OFF_DST + h * 64 + m] = s;
    }
    __syncthreads();

    // attention + cT[f][r]
    {
        const int fl = lane & 15, mb = (lane >> 4) * 32;
        for (int r = w * 16; r < w * 16 + 16; r++) {
            int h = r >> 5, n = r & 31;
            float sc = sm[OFF_SRC + h * 32 + n];
            float e1 = sc + sm[OFF_DST + h * 64 + lane];
            e1 = e1 > 0.f ? e1 : ALPHA * e1;
            if (!(sm[OFF_ADJ + n * 64 + lane] > 0.f)) e1 = NEGV;
            float e2 = sc + sm[OFF_DST + h * 64 + 32 + lane];
            e2 = e2 > 0.f ? e2 : ALPHA * e2;
            if (!(sm[OFF_ADJ + n * 64 + 32 + lane] > 0.f)) e2 = NEGV;
            float mx = fmaxf(e1, e2);
            #pragma unroll
            for (int o = 16; o; o >>= 1) mx = fmaxf(mx, __shfl_xor_sync(~0u, mx, o));
            float p1 = __expf(e1 - mx), p2 = __expf(e2 - mx);
            float su = p1 + p2;
            #pragma unroll
            for (int o = 16; o; o >>= 1) su += __shfl_xor_sync(~0u, su, o);
            float inv = 1.0f / su;
            sm[OFF_ATTN + w * 64 + lane]      = p1 * inv;
            sm[OFF_ATTN + w * 64 + 32 + lane] = p2 * inv;
            __syncwarp();
            float cc = 0.f;
            #pragma unroll
            for (int mm = 0; mm < 32; mm += 4) {
                float4 av = *(float4*)&sm[OFF_ATTN + w * 64 + mb + mm];
                float4 dv = *(float4*)&sm[OFF_DOCKT + fl * DKTLD + mb + mm];
                cc += av.x * dv.x + av.y * dv.y + av.z * dv.z + av.w * dv.w;
            }
            cc += __shfl_xor_sync(~0u, cc, 16);
            if (lane < 16) sm[OFF_CT + fl * CTLD + r] = cc;
            __syncwarp();
        }
    }
    __syncthreads();

    // h_drone (2 Wdock staging passes)
    float4 hacc[4] = {};
    for (int hp = 0; hp < 2; hp++) {
        for (int i = t; i < 1024; i += 256)
            *(float4*)&sm[OFF_SCR + i * 4] = *(const float4*)&Wdk[hp * 4096 + i * 4];
        __syncthreads();
        #pragma unroll
        for (int hf = 0; hf < 32; hf++) {
            float4 wv = *(float4*)&sm[OFF_SCR + hf * 128 + k4];
            float4 cv = *(float4*)&sm[OFF_CT + (hf & 15) * CTLD + (hp * 2 + (hf >> 4)) * 32 + w * 4];
            hacc[0].x += cv.x * wv.x; hacc[0].y += cv.x * wv.y; hacc[0].z += cv.x * wv.z; hacc[0].w += cv.x * wv.w;
            hacc[1].x += cv.y * wv.x; hacc[1].y += cv.y * wv.y; hacc[1].z += cv.y * wv.z; hacc[1].w += cv.y * wv.w;
            hacc[2].x += cv.z * wv.x; hacc[2].y += cv.z * wv.y; hacc[2].z += cv.z * wv.z; hacc[2].w += cv.z * wv.w;
            hacc[3].x += cv.w * wv.x; hacc[3].y += cv.w * wv.y; hacc[3].z += cv.w * wv.z; hacc[3].w += cv.w * wv.w;
        }
        __syncthreads();
    }
    {
        float4 ho[4];
        #pragma unroll
        for (int i = 0; i < 4; i++) {
            ho[i].x = eluf(hacc[i].x * 0.25f); ho[i].y = eluf(hacc[i].y * 0.25f);
            ho[i].z = eluf(hacc[i].z * 0.25f); ho[i].w = eluf(hacc[i].w * 0.25f);
        }
        float* hb = g_hdT + (size_t)b * 4096;
        *(float4*)&hb[(k4 + 0) * 32 + w * 4] = make_float4(ho[0].x, ho[1].x, ho[2].x, ho[3].x);
        *(float4*)&hb[(k4 + 1) * 32 + w * 4] = make_float4(ho[0].y, ho[1].y, ho[2].y, ho[3].y);
        *(float4*)&hb[(k4 + 2) * 32 + w * 4] = make_float4(ho[0].z, ho[1].z, ho[2].z, ho[3].z);
        *(float4*)&hb[(k4 + 3) * 32 + w * 4] = make_float4(ho[0].w, ho[1].w, ho[2].w, ho[3].w);
        // t[n] = hd[n,:].u + s0 via warp reduction
        float4 u4 = *(float4*)&sm[OFF_U + k4];
        float pt[4];
        #pragma unroll
        for (int i = 0; i < 4; i++)
            pt[i] = ho[i].x * u4.x + ho[i].y * u4.y + ho[i].z * u4.z + ho[i].w * u4.w;
        #pragma unroll
        for (int i = 0; i < 4; i++)
            #pragma unroll
            for (int o = 16; o; o >>= 1) pt[i] += __shfl_xor_sync(~0u, pt[i], o);
        if (lane == 0) {
            float s0v = g_s0[0];
            #pragma unroll
            for (int i = 0; i < 4; i++) g_t[b * 32 + w * 4 + i] = pt[i] + s0v;
        }
    }

    // h_dock -> g_hkT[b][k][m]
    for (int i = t; i < 512; i += 256)
        *(float4*)&sm[OFF_SCR + i * 4] = *(const float4*)&g_wbar[i * 4];
    __syncthreads();
    {
        const int m0 = (t & 7) * 8, k0 = (t >> 3) * 4;
        float4 acc[8] = {};
        #pragma unroll
        for (int f = 0; f < 16; f++) {
            float4 wv = *(float4*)&sm[OFF_SCR + f * 128 + k0];
            float4 da = *(float4*)&sm[OFF_DOCKT + f * DKTLD + m0];
            float4 db = *(float4*)&sm[OFF_DOCKT + f * DKTLD + m0 + 4];
            acc[0].x += da.x * wv.x; acc[0].y += da.x * wv.y; acc[0].z += da.x * wv.z; acc[0].w += da.x * wv.w;
            acc[1].x += da.y * wv.x; acc[1].y += da.y * wv.y; acc[1].z += da.y * wv.z; acc[1].w += da.y * wv.w;
            acc[2].x += da.z * wv.x; acc[2].y += da.z * wv.y; acc[2].z += da.z * wv.z; acc[2].w += da.z * wv.w;
            acc[3].x += da.w * wv.x; acc[3].y += da.w * wv.y; acc[3].z += da.w * wv.z; acc[3].w += da.w * wv.w;
            acc[4].x += db.x * wv.x; acc[4].y += db.x * wv.y; acc[4].z += db.x * wv.z; acc[4].w += db.x * wv.w;
            acc[5].x += db.y * wv.x; acc[5].y += db.y * wv.y; acc[5].z += db.y * wv.z; acc[5].w += db.y * wv.w;
            acc[6].x += db.z * wv.x; acc[6].y += db.z * wv.y; acc[6].z += db.z * wv.z; acc[6].w += db.z * wv.w;
            acc[7].x += db.w * wv.x; acc[7].y += db.w * wv.y; acc[7].z += db.w * wv.z; acc[7].w += db.w * wv.w;
        }
        float* kb = g_hkT + (size_t)b * 8192;
        #pragma unroll
        for (int q = 0; q < 4; q++) {
            float* accf = (float*)acc;
            float4 va = make_float4(eluf(accf[0 * 4 + q]), eluf(accf[1 * 4 + q]),
                                    eluf(accf[2 * 4 + q]), eluf(accf[3 * 4 + q]));
            float4 vb4 = make_float4(eluf(accf[4 * 4 + q]), eluf(accf[5 * 4 + q]),
                                     eluf(accf[6 * 4 + q]), eluf(accf[7 * 4 + q]));
            *(float4*)&kb[(k0 + q) * 64 + m0] = va;
            *(float4*)&kb[(k0 + q) * 64 + m0 + 4] = vb4;
        }
    }
}

// ================= R = HD @ M + vb (4 batches per CTA) =================
__global__ void __launch_bounds__(256) rmat_kernel()
{
    __shared__ float sM[4096], shT[4096], svb[128];
    const int t = threadIdx.x;
    const int b0 = blockIdx.x * 4;
    if (t < 128) svb[t] = g_vb[t];
    const int jt = t >> 4, rt = t & 15;
    const int j0 = jt * 8, r0 = rt * 8;
    float4 accA[8] = {}, accB[8] = {};

    for (int q = 0; q < 4; q++) {
        __syncthreads();
        for (int idx = t; idx < 1024; idx += 256) {
            int a = idx >> 5, c4 = (idx & 31) * 4;
            *(float4*)&sM[a * 128 + c4] = *(const float4*)&g_M[(q * 32 + a) * 128 + c4];
            int bb = c4 >> 5, n = c4 & 31;
            *(float4*)&shT[a * 128 + c4] =
                *(const float4*)&g_hdT[(size_t)(b0 + bb) * 4096 + (q * 32 + a) * 32 + n];
        }
        __syncthreads();
        #pragma unroll 4
        for (int a = 0; a < 32; a++) {
            float4 mv0 = *(float4*)&sM[a * 128 + j0];
            float4 mv1 = *(float4*)&sM[a * 128 + j0 + 4];
            float4 hv0 = *(float4*)&shT[a * 128 + r0];
            float4 hv1 = *(float4*)&shT[a * 128 + r0 + 4];
            accA[0].x += mv0.x * hv0.x; accA[0].y += mv0.x * hv0.y; accA[0].z += mv0.x * hv0.z; accA[0].w += mv0.x * hv0.w;
            accB[0].x += mv0.x * hv1.x; accB[0].y += mv0.x * hv1.y; accB[0].z += mv0.x * hv1.z; accB[0].w += mv0.x * hv1.w;
            accA[1].x += mv0.y * hv0.x; accA[1].y += mv0.y * hv0.y; accA[1].z += mv0.y * hv0.z; accA[1].w += mv0.y * hv0.w;
            accB[1].x += mv0.y * hv1.x; accB[1].y += mv0.y * hv1.y; accB[1].z += mv0.y * hv1.z; accB[1].w += mv0.y * hv1.w;
            accA[2].x += mv0.z * hv0.x; accA[2].y += mv0.z * hv0.y; accA[2].z += mv0.z * hv0.z; accA[2].w += mv0.z * hv0.w;
            accB[2].x += mv0.z * hv1.x; accB[2].y += mv0.z * hv1.y; accB[2].z += mv0.z * hv1.z; accB[2].w += mv0.z * hv1.w;
            accA[3].x += mv0.w * hv0.x; accA[3].y += mv0.w * hv0.y; accA[3].z += mv0.w * hv0.z; accA[3].w += mv0.w * hv0.w;
            accB[3].x += mv0.w * hv1.x; accB[3].y += mv0.w * hv1.y; accB[3].z += mv0.w * hv1.z; accB[3].w += mv0.w * hv1.w;
            accA[4].x += mv1.x * hv0.x; accA[4].y += mv1.x * hv0.y; accA[4].z += mv1.x * hv0.z; accA[4].w += mv1.x * hv0.w;
            accB[4].x += mv1.x * hv1.x; accB[4].y += mv1.x * hv1.y; accB[4].z += mv1.x * hv1.z; accB[4].w += mv1.x * hv1.w;
            accA[5].x += mv1.y * hv0.x; accA[5].y += mv1.y * hv0.y; accA[5].z += mv1.y * hv0.z; accA[5].w += mv1.y * hv0.w;
            accB[5].x += mv1.y * hv1.x; accB[5].y += mv1.y * hv1.y; accB[5].z += mv1.y * hv1.z; accB[5].w += mv1.y * hv1.w;
            accA[6].x += mv1.z * hv0.x; accA[6].y += mv1.z * hv0.y; accA[6].z += mv1.z * hv0.z; accA[6].w += mv1.z * hv0.w;
            accB[6].x += mv1.z * hv1.x; accB[6].y += mv1.z * hv1.y; accB[6].z += mv1.z * hv1.z; accB[6].w += mv1.z * hv1.w;
            accA[7].x += mv1.w * hv0.x; accA[7].y += mv1.w * hv0.y; accA[7].z += mv1.w * hv0.z; accA[7].w += mv1.w * hv0.w;
            accB[7].x += mv1.w * hv1.x; accB[7].y += mv1.w * hv1.y; accB[7].z += mv1.w * hv1.z; accB[7].w += mv1.w * hv1.w;
        }
    }
    const int bb = r0 >> 5, n0 = r0 & 31;
    float* rb = g_rT + ((size_t)(b0 + bb) * 128) * 32;
    #pragma unroll
    for (int jj = 0; jj < 8; jj++) {
        float vbj = svb[j0 + jj];
        float4 vA = accA[jj], vB = accB[jj];
        vA.x += vbj; vA.y += vbj; vA.z += vbj; vA.w += vbj;
        vB.x += vbj; vB.y += vbj; vB.z += vbj; vB.w += vbj;
        *(float4*)&rb[(j0 + jj) * 32 + n0] = vA;
        *(float4*)&rb[(j0 + jj) * 32 + n0 + 4] = vB;
    }
}

// ================= logits per batch =================
__global__ void __launch_bounds__(128) logits_kernel(
    const float* __restrict__ obs, float* __restrict__ out_logits)
{
    extern __shared__ float s4[];
    const int b = blockIdx.x, t = threadIdx.x;
    const float* rowp = obs + (size_t)b * OBSW;
    for (int i = t; i < 2048; i += 128) s4[L_ADJ + i] = rowp[1536 + i];
    for (int idx = t; idx < 1024; idx += 128) {
        int j = idx >> 3, n4 = (idx & 7) * 4;
        *(float4*)&s4[L_R + j * L_RLD + n4] = *(const float4*)&g_rT[((size_t)b * 128 + j) * 32 + n4];
    }
    for (int idx = t; idx < 2048; idx += 128) {
        int j = idx >> 4, m4 = (idx & 15) * 4;
        *(float4*)&s4[L_HK + j * L_HLD + m4] = *(const float4*)&g_hkT[(size_t)b * 8192 + j * 64 + m4];
    }
    if (t < 32) s4[L_T + t] = g_t[b * 32 + t];
    __syncthreads();

    const int n0 = (t >> 4) * 4, m0 = (t & 15) * 4;
    float4 acc[4] = {};
    #pragma unroll 4
    for (int j = 0; j < 128; j++) {
        float4 rv = *(float4*)&s4[L_R + j * L_RLD + n0];
        float4 hv = *(float4*)&s4[L_HK + j * L_HLD + m0];
        acc[0].x += rv.x * hv.x; acc[0].y += rv.x * hv.y; acc[0].z += rv.x * hv.z; acc[0].w += rv.x * hv.w;
        acc[1].x += rv.y * hv.x; acc[1].y += rv.y * hv.y; acc[1].z += rv.y * hv.z; acc[1].w += rv.y * hv.w;
        acc[2].x += rv.z * hv.x; acc[2].y += rv.z * hv.y; acc[2].z += rv.z * hv.z; acc[2].w += rv.z * hv.w;
        acc[3].x += rv.w * hv.x; acc[3].y += rv.w * hv.y; acc[3].z += rv.w * hv.z; acc[3].w += rv.w * hv.w;
    }
    float* op = out_logits + (size_t)b * 2048;
    #pragma unroll
    for (int i = 0; i < 4; i++) {
        int n = n0 + i;
        float tn = s4[L_T + n];
        float4 jv = *(float4*)&s4[L_ADJ + n * 64 + m0];
        float4 o;
        o.x = jv.x > 0.f ? acc[i].x + tn : NEGV;
        o.y = jv.y > 0.f ? acc[i].y + tn : NEGV;
        o.z = jv.z > 0.f ? acc[i].z + tn : NEGV;
        o.w = jv.w > 0.f ? acc[i].w + tn : NEGV;
        *(float4*)&op[n * 64 + m0] = o;
    }
}

// ================= critic GEMM (hdT-native) =================
__global__ void __launch_bounds__(256) critic_gemm()
{
    extern __shared__ float cs[];
    const int t = threadIdx.x;
    const int b0 = blockIdx.x * 256;
    const int kb = blockIdx.y * 512;
    const int bt = t >> 3, jt = t & 7;
    const int bl0 = bt * 8, j0 = jt * 8;
    float4 aJ0[8] = {}, aJ1[8] = {};

    for (int kc = 0; kc < 8; kc++) {
        const int kbase = kb + kc * 64;
        __syncthreads();
        for (int idx = t; idx < 4096; idx += 256) {
            int bq = idx >> 4, kq = idx & 15;
            *(float4*)&cs[bq * C_HLD + kq * 4] =
                *(const float4*)&g_hdT[(size_t)(b0 + bq) * 4096 + kbase + kq * 4];
        }
        for (int idx = t; idx < 1024; idx += 256) {
            int kl = idx >> 4, j4 = (idx & 15) * 4;
            *(float4*)&cs[C_SW + kl * 68 + j4] = *(const float4*)&g_Wc1p[(size_t)(kbase + kl) * 64 + j4];
        }
        __syncthreads();
        for (int kl = 0; kl < 64; kl++) {
            float4 wv0 = *(float4*)&cs[C_SW + kl * 68 + j0];
            float4 wv1 = *(float4*)&cs[C_SW + kl * 68 + j0 + 4];
            #pragma unroll
            for (int bb = 0; bb < 8; bb++) {
                float h = cs[(bl0 + bb) * C_HLD + kl];
                aJ0[bb].x += h * wv0.x; aJ0[bb].y += h * wv0.y; aJ0[bb].z += h * wv0.z; aJ0[bb].w += h * wv0.w;
                aJ1[bb].x += h * wv1.x; aJ1[bb].y += h * wv1.y; aJ1[bb].z += h * wv1.z; aJ1[bb].w += h * wv1.w;
            }
        }
    }
    #pragma unroll
    for (int bb = 0; bb < 8; bb++) {
        size_t o = ((size_t)blockIdx.y * NB + b0 + bl0 + bb) * 64 + j0;
        *(float4*)&g_hpart[o] = aJ0[bb];
        *(float4*)&g_hpart[o + 4] = aJ1[bb];
    }
}

__global__ void __launch_bounds__(256) critic_final(
    const float* __restrict__ bc1, const float* __restrict__ Wc2,
    const float* __restrict__ bc2, float* __restrict__ out_values)
{
    const int w = threadIdx.x >> 5, lane = threadIdx.x & 31;
    const int b = blockIdx.x * 8 + w;
    float a = 0.f;
    #pragma unroll
    for (int half = 0; half < 2; half++) {
        int jj = lane + 32 * half;
        size_t o = (size_t)b * 64 + jj;
        float h = bc1[jj];
        #pragma unroll
        for (int p = 0; p < 8; p++) h += g_hpart[(size_t)p * NB * 64 + o];
        a += (h > 0.f ? h : 0.f) * Wc2[jj];
    }
    #pragma unroll
    for (int o = 16; o; o >>= 1) a += __shfl_xor_sync(~0u, a, o);
    if (lane == 0) out_values[b] = a + bc2[0];
}

extern "C" void kernel_launch(void* const* d_in, const int* in_sizes, int n_in,
                              void* d_out, int out_size)
{
    const float* obs  = (const float*)d_in[0];
    const float* Wdr  = (const float*)d_in[1];
    const float* Wdk  = (const float*)d_in[2];
    const float* asrc = (const float*)d_in[3];
    const float* adst = (const float*)d_in[4];
    const float* Wc1  = (const float*)d_in[5];
    const float* bc1  = (const float*)d_in[6];
    const float* Wc2  = (const float*)d_in[7];
    const float* bc2  = (const float*)d_in[8];
    const float* Wad  = (const float*)d_in[9];
    const float* bad  = (const float*)d_in[10];
    const float* Wak  = (const float*)d_in[11];
    const float* bak  = (const float*)d_in[12];

    float* out        = (float*)d_out;
    float* out_values = out;
    float* out_logits = out + NB;

    cudaFuncSetAttribute(gat_attn, cudaFuncAttributeMaxDynamicSharedMemorySize, SMF2 * 4);
    cudaFuncSetAttribute(logits_kernel, cudaFuncAttributeMaxDynamicSharedMemorySize, L_SMF * 4);
    cudaFuncSetAttribute(critic_gemm, cudaFuncAttributeMaxDynamicSharedMemorySize, C_SMF * 4);

    precomp<<<17, 256>>>(Wdr, Wdk, asrc, adst, Wad, Wak, bad, bak);
    permute_wc1<<<16, 256>>>(Wc1);
    gat_attn<<<NB, 256, SMF2 * 4>>>(obs, Wdk);
    rmat_kernel<<<NB / 4, 256>>>();
    logits_kernel<<<NB, 128, L_SMF * 4>>>(obs, out_logits);
    critic_gemm<<<dim3(16, 8), 256, C_SMF * 4>>>();
    critic_final<<<NB / 8, 256>>>(bc1, Wc2, bc2, out_values);
}

// round 6
// speedup vs baseline: 1.1751x; 1.1751x over previous
#include <cuda_runtime.h>

#define NB 4096
#define ND 32
#define NK 64
#define NHID 128
#define ALPHA 0.2f
#define NEGV (-9e15f)
#define OBSW 3584

// ---- gat_main smem layout (float offsets) ---- (identical to R4)
#define OFF_ADJ   0
#define OFF_DOCKT 2048
#define DKTLD 68
#define OFF_DRONE 3136
#define OFF_HDT   3648
#define HDTLD 36
#define OFF_HKT   8256
#define HKTLD 68
#define OFF_RT    16960
#define RTLD 36
#define OFF_CT    16960
#define CTLD 132
#define OFF_SCR   21568
#define OFF_ATTN  25664
#define OFF_SRC   26176
#define OFF_DST   26304
#define OFF_VS    26560
#define OFF_VD    26624
#define OFF_VB    26688
#define OFF_U     26816
#define OFF_T     26944
#define SMF       26976

typedef unsigned long long u64;

__device__ __forceinline__ u64 pk2(float lo, float hi) {
    u64 r; asm("mov.b64 %0,{%1,%2};" : "=l"(r) : "f"(lo), "f"(hi)); return r;
}
__device__ __forceinline__ void fma2(u64& d, u64 a, u64 b) {
    asm("fma.rn.f32x2 %0, %1, %2, %0;" : "+l"(d) : "l"(a), "l"(b));
}
__device__ __forceinline__ float2 up2(u64 v) {
    float2 f; asm("mov.b64 {%0,%1},%2;" : "=f"(f.x), "=f"(f.y) : "l"(v)); return f;
}

__device__ float g_hd[(size_t)NB * ND * NHID];   // 64 MB
__device__ float g_hpart[8ull * NB * 64];        // 8 MB critic partials
__device__ float g_M[NHID * NHID];
__device__ float g_vb[NHID];
__device__ float g_u[NHID];
__device__ float g_s0[1];
__device__ float g_vsrc[64];
__device__ float g_vdst[64];
__device__ float g_wbar[16 * NHID];

__device__ __forceinline__ float eluf(float x) { return x > 0.f ? x : expm1f(x); }

// ================= precompute (batch-independent), grid=17 =================
__global__ void precomp(const float* __restrict__ Wdr, const float* __restrict__ Wdk,
                        const float* __restrict__ asrc, const float* __restrict__ adst,
                        const float* __restrict__ Wad, const float* __restrict__ Wak,
                        const float* __restrict__ bad, const float* __restrict__ bak)
{
    const int t = threadIdx.x;
    if (blockIdx.x < 16) {
        __shared__ float swad[8 * 128];
        __shared__ float swak[32 * 128];
        const int a0 = blockIdx.x * 8;
        for (int i = t; i < 1024; i += 256) swad[i] = Wad[a0 * 128 + i];
        for (int jb = 0; jb < 4; jb++) {
            __syncthreads();
            for (int i = t; i < 4096; i += 256) swak[i] = Wak[jb * 4096 + i];
            __syncthreads();
            const int aa = t >> 5, jl = t & 31;
            float s = 0.f;
            for (int c = 0; c < 128; c++) {
                int cc = (c + jl) & 127;
                s += swad[aa * 128 + cc] * swak[jl * 128 + cc];
            }
            g_M[(a0 + aa) * 128 + jb * 32 + jl] = s;
        }
        if (t < 8) {
            float s = 0.f;
            for (int c = 0; c < 128; c++) s += swad[t * 128 + c] * bak[c];
            g_u[a0 + t] = s;
        }
    } else {
        __shared__ float sb[128];
        if (t < 128) sb[t] = bad[t];
        __syncthreads();
        if (t < 128) {
            float s = 0.f;
            for (int c = 0; c < 128; c++) s += sb[c] * Wak[t * 128 + c];
            g_vb[t] = s;
        }
        if (t == 0) {
            float s = 0.f;
            for (int c = 0; c < 128; c++) s += sb[c] * bak[c];
            g_s0[0] = s;
        }
        if (t < 64) {
            int h = t >> 4, f = t & 15;
            float s = 0.f;
            for (int c = 0; c < 128; c++) s += Wdr[(h * 16 + f) * 128 + c] * asrc[h * 128 + c];
            g_vsrc[t] = s;
        } else if (t < 128) {
            int u2 = t - 64, h = u2 >> 4, f = u2 & 15;
            float s = 0.f;
            for (int c = 0; c < 128; c++) s += Wdk[(h * 16 + f) * 128 + c] * adst[h * 128 + c];
            g_vdst[u2] = s;
        }
        for (int i = t; i < 2048; i += 256) {
            float s = Wdk[i] + Wdk[2048 + i] + Wdk[4096 + i] + Wdk[6144 + i];
            g_wbar[i] = s * 0.25f;
        }
    }
}

// ================= per-batch kernel =================
__global__ void __launch_bounds__(256, 2) gat_main(
    const float* __restrict__ obs, const float* __restrict__ Wdk,
    float* __restrict__ out_logits)
{
    extern __shared__ float sm[];
    const int b = blockIdx.x, t = threadIdx.x;
    const int w = t >> 5, lane = t & 31;
    const int k4 = lane * 4;
    const float* rowp = obs + (size_t)b * OBSW;

    for (int i = t; i < 512;  i += 256) sm[OFF_DRONE + i] = rowp[i];
    for (int i = t; i < 1024; i += 256) {
        int m = i >> 4, f = i & 15;
        sm[OFF_DOCKT + f * DKTLD + m] = rowp[512 + i];
    }
    for (int i = t; i < 2048; i += 256) sm[OFF_ADJ + i] = rowp[1536 + i];
    if (t < 64)       sm[OFF_VS + t]       = g_vsrc[t];
    else if (t < 128) sm[OFF_VD + t - 64]  = g_vdst[t - 64];
    else              sm[OFF_VB + t - 128] = g_vb[t - 128];
    for (int i = t; i < 128; i += 256) sm[OFF_U + i] = g_u[i];
    __syncthreads();

    // src[h,n], dst[h,m]
    if (t < 128) {
        int h = t >> 5, n = t & 31;
        float s = 0.f;
        #pragma unroll
        for (int f = 0; f < 16; f++) s += sm[OFF_DRONE + n * 16 + f] * sm[OFF_VS + h * 16 + f];
        sm[OFF_SRC + t] = s;
    }
    {
        int h = t >> 6, m = t & 63;
        float s = 0.f;
        #pragma unroll
        for (int f = 0; f < 16; f++) s += sm[OFF_DOCKT + f * DKTLD + m] * sm[OFF_VD + h * 16 + f];
        sm[OFF_DST + h * 64 + m] = s;
    }
    __syncthreads();

    // attention: softmax + cT[f][r]
    {
        const int fl = lane & 15, mb = (lane >> 4) * 32;
        for (int r = w * 16; r < w * 16 + 16; r++) {
            int h = r >> 5, n = r & 31;
            float sc = sm[OFF_SRC + h * 32 + n];
            float e1 = sc + sm[OFF_DST + h * 64 + lane];
            e1 = e1 > 0.f ? e1 : ALPHA * e1;
            if (!(sm[OFF_ADJ + n * 64 + lane] > 0.f)) e1 = NEGV;
            float e2 = sc + sm[OFF_DST + h * 64 + 32 + lane];
            e2 = e2 > 0.f ? e2 : ALPHA * e2;
            if (!(sm[OFF_ADJ + n * 64 + 32 + lane] > 0.f)) e2 = NEGV;
            float mx = fmaxf(e1, e2);
            #pragma unroll
            for (int o = 16; o; o >>= 1) mx = fmaxf(mx, __shfl_xor_sync(~0u, mx, o));
            float p1 = __expf(e1 - mx), p2 = __expf(e2 - mx);
            float su = p1 + p2;
            #pragma unroll
            for (int o = 16; o; o >>= 1) su += __shfl_xor_sync(~0u, su, o);
            float inv = 1.0f / su;
            sm[OFF_ATTN + w * 64 + lane]      = p1 * inv;
            sm[OFF_ATTN + w * 64 + 32 + lane] = p2 * inv;
            __syncwarp();
            float cc = 0.f;
            #pragma unroll
            for (int mm = 0; mm < 32; mm += 4) {
                float4 av = *(float4*)&sm[OFF_ATTN + w * 64 + mb + mm];
                float4 dv = *(float4*)&sm[OFF_DOCKT + fl * DKTLD + mb + mm];
                cc += av.x * dv.x + av.y * dv.y + av.z * dv.z + av.w * dv.w;
            }
            cc += __shfl_xor_sync(~0u, cc, 16);
            if (lane < 16) sm[OFF_CT + fl * CTLD + r] = cc;
            __syncwarp();
        }
    }
    __syncthreads();

    // h_drone (FFMA2): 2 head-pair passes, warp w owns n = w*4..+3, lane owns k4..k4+3
    u64 hacc2[8] = {};
    for (int hp = 0; hp < 2; hp++) {
        for (int i = t; i < 1024; i += 256)
            *(float4*)&sm[OFF_SCR + i * 4] = *(const float4*)&Wdk[hp * 4096 + i * 4];
        __syncthreads();
        #pragma unroll
        for (int hf = 0; hf < 32; hf++) {
            ulonglong2 wv = *(ulonglong2*)&sm[OFF_SCR + hf * 128 + k4];
            float4 cv = *(float4*)&sm[OFF_CT + (hf & 15) * CTLD + (hp * 2 + (hf >> 4)) * 32 + w * 4];
            u64 c0 = pk2(cv.x, cv.x), c1 = pk2(cv.y, cv.y);
            u64 c2 = pk2(cv.z, cv.z), c3 = pk2(cv.w, cv.w);
            fma2(hacc2[0], c0, wv.x); fma2(hacc2[1], c0, wv.y);
            fma2(hacc2[2], c1, wv.x); fma2(hacc2[3], c1, wv.y);
            fma2(hacc2[4], c2, wv.x); fma2(hacc2[5], c2, wv.y);
            fma2(hacc2[6], c3, wv.x); fma2(hacc2[7], c3, wv.y);
        }
        __syncthreads();
    }
    {
        float4 ho[4];
        #pragma unroll
        for (int i = 0; i < 4; i++) {
            float2 lo = up2(hacc2[2 * i]), hi = up2(hacc2[2 * i + 1]);
            ho[i].x = eluf(lo.x * 0.25f); ho[i].y = eluf(lo.y * 0.25f);
            ho[i].z = eluf(hi.x * 0.25f); ho[i].w = eluf(hi.y * 0.25f);
            *(float4*)&g_hd[((size_t)b * ND + w * 4 + i) * 128 + k4] = ho[i];
        }
        *(float4*)&sm[OFF_HDT + (k4 + 0) * HDTLD + w * 4] = make_float4(ho[0].x, ho[1].x, ho[2].x, ho[3].x);
        *(float4*)&sm[OFF_HDT + (k4 + 1) * HDTLD + w * 4] = make_float4(ho[0].y, ho[1].y, ho[2].y, ho[3].y);
        *(float4*)&sm[OFF_HDT + (k4 + 2) * HDTLD + w * 4] = make_float4(ho[0].z, ho[1].z, ho[2].z, ho[3].z);
        *(float4*)&sm[OFF_HDT + (k4 + 3) * HDTLD + w * 4] = make_float4(ho[0].w, ho[1].w, ho[2].w, ho[3].w);
    }

    // h_dock (FFMA2): stage wbar; tile 8m x 4k, packed along k -> hkT[k][m]
    for (int i = t; i < 512; i += 256)
        *(float4*)&sm[OFF_SCR + i * 4] = *(const float4*)&g_wbar[i * 4];
    __syncthreads();
    {
        const int m0 = (t & 7) * 8, k0 = (t >> 3) * 4;
        u64 acc2[8][2] = {};
        #pragma unroll
        for (int f = 0; f < 16; f++) {
            ulonglong2 wv = *(ulonglong2*)&sm[OFF_SCR + f * 128 + k0];
            float4 da = *(float4*)&sm[OFF_DOCKT + f * DKTLD + m0];
            float4 db = *(float4*)&sm[OFF_DOCKT + f * DKTLD + m0 + 4];
            u64 d0 = pk2(da.x, da.x), d1 = pk2(da.y, da.y), d2 = pk2(da.z, da.z), d3 = pk2(da.w, da.w);
            u64 d4 = pk2(db.x, db.x), d5 = pk2(db.y, db.y), d6 = pk2(db.z, db.z), d7 = pk2(db.w, db.w);
            fma2(acc2[0][0], d0, wv.x); fma2(acc2[0][1], d0, wv.y);
            fma2(acc2[1][0], d1, wv.x); fma2(acc2[1][1], d1, wv.y);
            fma2(acc2[2][0], d2, wv.x); fma2(acc2[2][1], d2, wv.y);
            fma2(acc2[3][0], d3, wv.x); fma2(acc2[3][1], d3, wv.y);
            fma2(acc2[4][0], d4, wv.x); fma2(acc2[4][1], d4, wv.y);
            fma2(acc2[5][0], d5, wv.x); fma2(acc2[5][1], d5, wv.y);
            fma2(acc2[6][0], d6, wv.x); fma2(acc2[6][1], d6, wv.y);
            fma2(acc2[7][0], d7, wv.x); fma2(acc2[7][1], d7, wv.y);
        }
        float accf[8][4];
        #pragma unroll
        for (int m = 0; m < 8; m++) {
            float2 a = up2(acc2[m][0]), bq = up2(acc2[m][1]);
            accf[m][0] = a.x; accf[m][1] = a.y; accf[m][2] = bq.x; accf[m][3] = bq.y;
        }
        #pragma unroll
        for (int q = 0; q < 4; q++) {
            float4 va = make_float4(eluf(accf[0][q]), eluf(accf[1][q]), eluf(accf[2][q]), eluf(accf[3][q]));
            float4 vb4 = make_float4(eluf(accf[4][q]), eluf(accf[5][q]), eluf(accf[6][q]), eluf(accf[7][q]));
            *(float4*)&sm[OFF_HKT + (k0 + q) * HKTLD + m0] = va;
            *(float4*)&sm[OFF_HKT + (k0 + q) * HKTLD + m0 + 4] = vb4;
        }
    }
    __syncthreads();

    // r = hd @ M + vb (FFMA2): tile 2n x 8j, packed along j; M staged in 4 quarters
    {
        const int n0 = (t & 15) * 2, j0 = (t >> 4) * 8;
        u64 acc2[2][4] = {};
        for (int q = 0; q < 4; q++) {
            for (int i = t; i < 1024; i += 256)
                *(float4*)&sm[OFF_SCR + i * 4] = *(const float4*)&g_M[q * 4096 + i * 4];
            __syncthreads();
            #pragma unroll 8
            for (int al = 0; al < 32; al++) {
                ulonglong2 m01 = *(ulonglong2*)&sm[OFF_SCR + al * 128 + j0];
                ulonglong2 m23 = *(ulonglong2*)&sm[OFF_SCR + al * 128 + j0 + 4];
                float2 hv = *(float2*)&sm[OFF_HDT + (q * 32 + al) * HDTLD + n0];
                u64 h0 = pk2(hv.x, hv.x), h1 = pk2(hv.y, hv.y);
                fma2(acc2[0][0], h0, m01.x); fma2(acc2[0][1], h0, m01.y);
                fma2(acc2[0][2], h0, m23.x); fma2(acc2[0][3], h0, m23.y);
                fma2(acc2[1][0], h1, m01.x); fma2(acc2[1][1], h1, m01.y);
                fma2(acc2[1][2], h1, m23.x); fma2(acc2[1][3], h1, m23.y);
            }
            __syncthreads();
        }
        #pragma unroll
        for (int jp = 0; jp < 4; jp++) {
            float2 a0 = up2(acc2[0][jp]);   // rows n0, cols j0+2jp, j0+2jp+1
            float2 a1 = up2(acc2[1][jp]);   // rows n0+1
            float vb0 = sm[OFF_VB + j0 + 2 * jp], vb1 = sm[OFF_VB + j0 + 2 * jp + 1];
            *(float2*)&sm[OFF_RT + (j0 + 2 * jp) * RTLD + n0]     = make_float2(a0.x + vb0, a1.x + vb0);
            *(float2*)&sm[OFF_RT + (j0 + 2 * jp + 1) * RTLD + n0] = make_float2(a0.y + vb1, a1.y + vb1);
        }
    }
    // t[n] = hd[n,:].u + s0
    if (t < 32) {
        float s = g_s0[0];
        #pragma unroll 8
        for (int a = 0; a < 128; a++) s += sm[OFF_HDT + a * HDTLD + t] * sm[OFF_U + a];
        sm[OFF_T + t] = s;
    }
    __syncthreads();

    // logits (FFMA2): tile 2n x 4m, packed along m
    {
        const int n0 = (t >> 4) * 2, m0 = (t & 15) * 4;
        u64 acc2[2][2] = {};
        #pragma unroll 4
        for (int j = 0; j < 128; j++) {
            float2 rv = *(float2*)&sm[OFF_RT + j * RTLD + n0];
            ulonglong2 hv = *(ulonglong2*)&sm[OFF_HKT + j * HKTLD + m0];
            u64 r0 = pk2(rv.x, rv.x), r1 = pk2(rv.y, rv.y);
            fma2(acc2[0][0], r0, hv.x); fma2(acc2[0][1], r0, hv.y);
            fma2(acc2[1][0], r1, hv.x); fma2(acc2[1][1], r1, hv.y);
        }
        float2 p00 = up2(acc2[0][0]), p01 = up2(acc2[0][1]);
        float2 p10 = up2(acc2[1][0]), p11 = up2(acc2[1][1]);
        float t0 = sm[OFF_T + n0], t1 = sm[OFF_T + n0 + 1];
        float4 j0v = *(float4*)&sm[OFF_ADJ + n0 * 64 + m0];
        float4 j1v = *(float4*)&sm[OFF_ADJ + (n0 + 1) * 64 + m0];
        float4 o0, o1;
        o0.x = j0v.x > 0.f ? p00.x + t0 : NEGV; o0.y = j0v.y > 0.f ? p00.y + t0 : NEGV;
        o0.z = j0v.z > 0.f ? p01.x + t0 : NEGV; o0.w = j0v.w > 0.f ? p01.y + t0 : NEGV;
        o1.x = j1v.x > 0.f ? p10.x + t1 : NEGV; o1.y = j1v.y > 0.f ? p10.y + t1 : NEGV;
        o1.z = j1v.z > 0.f ? p11.x + t1 : NEGV; o1.w = j1v.w > 0.f ? p11.y + t1 : NEGV;
        float* op = out_logits + (size_t)b * 2048;
        *(float4*)&op[n0 * 64 + m0] = o0;
        *(float4*)&op[(n0 + 1) * 64 + m0] = o1;
    }
}

// ================= critic: split-K(8) GEMM then combine (R4-identical) =================
__global__ void __launch_bounds__(256) critic_gemm(const float* __restrict__ Wc1)
{
    __shared__ float s_chunk[32 * 128];
    const int t = threadIdx.x;
    const int b0 = blockIdx.x * 32;
    const int kb = blockIdx.y * 512;
    const int j = t & 63, rg = t >> 6;
    float acc[8] = {};

    for (int c = 0; c < 4; c++) {
        const int kbase = kb + c * 128;
        __syncthreads();
        for (int idx = t; idx < 1024; idx += 256) {
            int r = idx >> 5, c4 = (idx & 31) * 4;
            *(float4*)&s_chunk[r * 128 + c4] =
                *(const float4*)&g_hd[(size_t)(b0 + r) * 4096 + kbase + c4];
        }
        __syncthreads();
        for (int ii = 0; ii < 128; ii += 4) {
            float w0 = Wc1[(size_t)(kbase + ii    ) * 64 + j];
            float w1 = Wc1[(size_t)(kbase + ii + 1) * 64 + j];
            float w2 = Wc1[(size_t)(kbase + ii + 2) * 64 + j];
            float w3 = Wc1[(size_t)(kbase + ii + 3) * 64 + j];
            #pragma unroll
            for (int r = 0; r < 8; r++) {
                float4 h4 = *(const float4*)&s_chunk[(rg * 8 + r) * 128 + ii];
                acc[r] += h4.x * w0 + h4.y * w1 + h4.z * w2 + h4.w * w3;
            }
        }
    }
    #pragma unroll
    for (int r = 0; r < 8; r++)
        g_hpart[((size_t)blockIdx.y * NB + b0 + rg * 8 + r) * 64 + j] = acc[r];
}

__global__ void __launch_bounds__(256) critic_final(
    const float* __restrict__ bc1, const float* __restrict__ Wc2,
    const float* __restrict__ bc2, float* __restrict__ out_values)
{
    const int w = threadIdx.x >> 5, lane = threadIdx.x & 31;
    const int b = blockIdx.x * 8 + w;
    float a = 0.f;
    #pragma unroll
    for (int half = 0; half < 2; half++) {
        int jj = lane + 32 * half;
        size_t o = (size_t)b * 64 + jj;
        float h = bc1[jj];
        #pragma unroll
        for (int p = 0; p < 8; p++) h += g_hpart[(size_t)p * NB * 64 + o];
        a += (h > 0.f ? h : 0.f) * Wc2[jj];
    }
    #pragma unroll
    for (int o = 16; o; o >>= 1) a += __shfl_xor_sync(~0u, a, o);
    if (lane == 0) out_values[b] = a + bc2[0];
}

extern "C" void kernel_launch(void* const* d_in, const int* in_sizes, int n_in,
                              void* d_out, int out_size)
{
    const float* obs  = (const float*)d_in[0];
    const float* Wdr  = (const float*)d_in[1];
    const float* Wdk  = (const float*)d_in[2];
    const float* asrc = (const float*)d_in[3];
    const float* adst = (const float*)d_in[4];
    const float* Wc1  = (const float*)d_in[5];
    const float* bc1  = (const float*)d_in[6];
    const float* Wc2  = (const float*)d_in[7];
    const float* bc2  = (const float*)d_in[8];
    const float* Wad  = (const float*)d_in[9];
    const float* bad  = (const float*)d_in[10];
    const float* Wak  = (const float*)d_in[11];
    const float* bak  = (const float*)d_in[12];

    float* out        = (float*)d_out;
    float* out_values = out;
    float* out_logits = out + NB;

    cudaFuncSetAttribute(gat_main, cudaFuncAttributeMaxDynamicSharedMemorySize,
                         SMF * (int)sizeof(float));

    precomp<<<17, 256>>>(Wdr, Wdk, asrc, adst, Wad, Wak, bad, bak);
    gat_main<<<NB, 256, SMF * sizeof(float)>>>(obs, Wdk, out_logits);
    critic_gemm<<<dim3(NB / 32, 8), 256>>>(Wc1);
    critic_final<<<NB / 8, 256>>>(bc1, Wc2, bc2, out_values);
}

// round 7
// speedup vs baseline: 1.3253x; 1.1278x over previous
#include <cuda_runtime.h>

#define NB 4096
#define ND 32
#define NK 64
#define NHID 128
#define ALPHA 0.2f
#define NEGV (-9e15f)
#define OBSW 3584

// ---- gat_main smem layout (float offsets), phase-lifetime aliased ----
#define OFF_ADJ   0        // 2048   (dead after attention)
#define OFF_DOCKT 2048     // 1088   (dead after h_dock)
#define DKTLD 68
#define OFF_CT    3136     // 2112   (dead after h_drone)
#define CTLD 132
#define OFF_RT    0        // 4608   (written in r-GEMM, over ADJ/DOCKT/CT)
#define RTLD 36
#define OFF_HDT   5248     // 4608
#define HDTLD 36
#define OFF_DRONE 5248     // 512  alias in HDT (dead before HDT write)
#define OFF_ATTN  5760     // 512  alias in HDT
#define OFF_HKT   9856     // 8704
#define HKTLD 68
#define OFF_SRC   9856     // 128  alias in HKT (dead before HKT write)
#define OFF_DST   9984     // 256  alias in HKT
#define OFF_VS    10240    // 64   alias in HKT
#define OFF_VD    10304    // 64   alias in HKT
#define OFF_VB    18560    // 128
#define OFF_U     18688    // 128
#define OFF_T     18816    // 32
#define SMF       18848    // 75392 B -> 3 CTAs/SM

typedef unsigned long long u64;

__device__ __forceinline__ u64 pk2(float lo, float hi) {
    u64 r; asm("mov.b64 %0,{%1,%2};" : "=l"(r) : "f"(lo), "f"(hi)); return r;
}
__device__ __forceinline__ void fma2(u64& d, u64 a, u64 b) {
    asm("fma.rn.f32x2 %0, %1, %2, %0;" : "+l"(d) : "l"(a), "l"(b));
}
__device__ __forceinline__ float2 up2(u64 v) {
    float2 f; asm("mov.b64 {%0,%1},%2;" : "=f"(f.x), "=f"(f.y) : "l"(v)); return f;
}

__device__ float g_hd[(size_t)NB * ND * NHID];   // 64 MB
__device__ float g_hpart[8ull * NB * 64];        // 8 MB critic partials
__device__ float g_M[NHID * NHID];
__device__ float g_vb[NHID];
__device__ float g_u[NHID];
__device__ float g_s0[1];
__device__ float g_vsrc[64];
__device__ float g_vdst[64];
__device__ float g_wbar[16 * NHID];

__device__ __forceinline__ float eluf(float x) { return x > 0.f ? x : expm1f(x); }

// ================= precompute (batch-independent), grid=17 =================
__global__ void precomp(const float* __restrict__ Wdr, const float* __restrict__ Wdk,
                        const float* __restrict__ asrc, const float* __restrict__ adst,
                        const float* __restrict__ Wad, const float* __restrict__ Wak,
                        const float* __restrict__ bad, const float* __restrict__ bak)
{
    const int t = threadIdx.x;
    if (blockIdx.x < 16) {
        __shared__ float swad[8 * 128];
        __shared__ float swak[32 * 128];
        const int a0 = blockIdx.x * 8;
        for (int i = t; i < 1024; i += 256) swad[i] = Wad[a0 * 128 + i];
        for (int jb = 0; jb < 4; jb++) {
            __syncthreads();
            for (int i = t; i < 4096; i += 256) swak[i] = Wak[jb * 4096 + i];
            __syncthreads();
            const int aa = t >> 5, jl = t & 31;
            float s = 0.f;
            for (int c = 0; c < 128; c++) {
                int cc = (c + jl) & 127;
                s += swad[aa * 128 + cc] * swak[jl * 128 + cc];
            }
            g_M[(a0 + aa) * 128 + jb * 32 + jl] = s;
        }
        if (t < 8) {
            float s = 0.f;
            for (int c = 0; c < 128; c++) s += swad[t * 128 + c] * bak[c];
            g_u[a0 + t] = s;
        }
    } else {
        __shared__ float sb[128];
        if (t < 128) sb[t] = bad[t];
        __syncthreads();
        if (t < 128) {
            float s = 0.f;
            for (int c = 0; c < 128; c++) s += sb[c] * Wak[t * 128 + c];
            g_vb[t] = s;
        }
        if (t == 0) {
            float s = 0.f;
            for (int c = 0; c < 128; c++) s += sb[c] * bak[c];
            g_s0[0] = s;
        }
        if (t < 64) {
            int h = t >> 4, f = t & 15;
            float s = 0.f;
            for (int c = 0; c < 128; c++) s += Wdr[(h * 16 + f) * 128 + c] * asrc[h * 128 + c];
            g_vsrc[t] = s;
        } else if (t < 128) {
            int u2 = t - 64, h = u2 >> 4, f = u2 & 15;
            float s = 0.f;
            for (int c = 0; c < 128; c++) s += Wdk[(h * 16 + f) * 128 + c] * adst[h * 128 + c];
            g_vdst[u2] = s;
        }
        for (int i = t; i < 2048; i += 256) {
            float s = Wdk[i] + Wdk[2048 + i] + Wdk[4096 + i] + Wdk[6144 + i];
            g_wbar[i] = s * 0.25f;
        }
    }
}

// ================= per-batch kernel =================
__global__ void __launch_bounds__(256, 3) gat_main(
    const float* __restrict__ obs, const float* __restrict__ Wdk,
    float* __restrict__ out_logits)
{
    extern __shared__ float sm[];
    const int b = blockIdx.x, t = threadIdx.x;
    const int w = t >> 5, lane = t & 31;
    const int k4 = lane * 4;
    const float* rowp = obs + (size_t)b * OBSW;

    // ---- 1. load per-batch data ----
    for (int i = t; i < 512;  i += 256) sm[OFF_DRONE + i] = rowp[i];
    for (int i = t; i < 1024; i += 256) {
        int m = i >> 4, f = i & 15;
        sm[OFF_DOCKT + f * DKTLD + m] = rowp[512 + i];
    }
    for (int i = t; i < 2048; i += 256) sm[OFF_ADJ + i] = rowp[1536 + i];
    if (t < 64)       sm[OFF_VS + t]       = g_vsrc[t];
    else if (t < 128) sm[OFF_VD + t - 64]  = g_vdst[t - 64];
    else              sm[OFF_VB + t - 128] = g_vb[t - 128];
    for (int i = t; i < 128; i += 256) sm[OFF_U + i] = g_u[i];
    __syncthreads();

    // ---- 2. src[h,n], dst[h,m] ----
    if (t < 128) {
        int h = t >> 5, n = t & 31;
        float s = 0.f;
        #pragma unroll
        for (int f = 0; f < 16; f++) s += sm[OFF_DRONE + n * 16 + f] * sm[OFF_VS + h * 16 + f];
        sm[OFF_SRC + t] = s;
    }
    {
        int h = t >> 6, m = t & 63;
        float s = 0.f;
        #pragma unroll
        for (int f = 0; f < 16; f++) s += sm[OFF_DOCKT + f * DKTLD + m] * sm[OFF_VD + h * 16 + f];
        sm[OFF_DST + h * 64 + m] = s;
    }
    __syncthreads();

    // ---- 3. attention: softmax + cT[f][r] ----
    {
        const int fl = lane & 15, mb = (lane >> 4) * 32;
        for (int r = w * 16; r < w * 16 + 16; r++) {
            int h = r >> 5, n = r & 31;
            float sc = sm[OFF_SRC + h * 32 + n];
            float e1 = sc + sm[OFF_DST + h * 64 + lane];
            e1 = e1 > 0.f ? e1 : ALPHA * e1;
            if (!(sm[OFF_ADJ + n * 64 + lane] > 0.f)) e1 = NEGV;
            float e2 = sc + sm[OFF_DST + h * 64 + 32 + lane];
            e2 = e2 > 0.f ? e2 : ALPHA * e2;
            if (!(sm[OFF_ADJ + n * 64 + 32 + lane] > 0.f)) e2 = NEGV;
            float mx = fmaxf(e1, e2);
            #pragma unroll
            for (int o = 16; o; o >>= 1) mx = fmaxf(mx, __shfl_xor_sync(~0u, mx, o));
            float p1 = __expf(e1 - mx), p2 = __expf(e2 - mx);
            float su = p1 + p2;
            #pragma unroll
            for (int o = 16; o; o >>= 1) su += __shfl_xor_sync(~0u, su, o);
            float inv = 1.0f / su;
            sm[OFF_ATTN + w * 64 + lane]      = p1 * inv;
            sm[OFF_ATTN + w * 64 + 32 + lane] = p2 * inv;
            __syncwarp();
            float cc = 0.f;
            #pragma unroll
            for (int mm = 0; mm < 32; mm += 4) {
                float4 av = *(float4*)&sm[OFF_ATTN + w * 64 + mb + mm];
                float4 dv = *(float4*)&sm[OFF_DOCKT + fl * DKTLD + mb + mm];
                cc += av.x * dv.x + av.y * dv.y + av.z * dv.z + av.w * dv.w;
            }
            cc += __shfl_xor_sync(~0u, cc, 16);
            if (lane < 16) sm[OFF_CT + fl * CTLD + r] = cc;
            __syncwarp();
        }
    }
    __syncthreads();

    // ---- 4. h_drone (FFMA2, Wdk from gmem): warp w owns n=w*4..+3, lane owns k4 ----
    u64 hacc2[8] = {};
    #pragma unroll 4
    for (int hf = 0; hf < 64; hf++) {
        ulonglong2 wv = *(const ulonglong2*)&Wdk[hf * 128 + k4];
        float4 cv = *(float4*)&sm[OFF_CT + (hf & 15) * CTLD + (hf >> 4) * 32 + w * 4];
        u64 c0 = pk2(cv.x, cv.x), c1 = pk2(cv.y, cv.y);
        u64 c2 = pk2(cv.z, cv.z), c3 = pk2(cv.w, cv.w);
        fma2(hacc2[0], c0, wv.x); fma2(hacc2[1], c0, wv.y);
        fma2(hacc2[2], c1, wv.x); fma2(hacc2[3], c1, wv.y);
        fma2(hacc2[4], c2, wv.x); fma2(hacc2[5], c2, wv.y);
        fma2(hacc2[6], c3, wv.x); fma2(hacc2[7], c3, wv.y);
    }
    {
        float4 ho[4];
        #pragma unroll
        for (int i = 0; i < 4; i++) {
            float2 lo = up2(hacc2[2 * i]), hi = up2(hacc2[2 * i + 1]);
            ho[i].x = eluf(lo.x * 0.25f); ho[i].y = eluf(lo.y * 0.25f);
            ho[i].z = eluf(hi.x * 0.25f); ho[i].w = eluf(hi.y * 0.25f);
            *(float4*)&g_hd[((size_t)b * ND + w * 4 + i) * 128 + k4] = ho[i];
        }
        // t[n] = hd[n,:].u + s0 via warp reduce (before HDT overwrite is fine: regs)
        float4 u4 = *(float4*)&sm[OFF_U + k4];
        float pt[4];
        #pragma unroll
        for (int i = 0; i < 4; i++)
            pt[i] = ho[i].x * u4.x + ho[i].y * u4.y + ho[i].z * u4.z + ho[i].w * u4.w;
        #pragma unroll
        for (int i = 0; i < 4; i++)
            #pragma unroll
            for (int o = 16; o; o >>= 1) pt[i] += __shfl_xor_sync(~0u, pt[i], o);
        __syncthreads();   // ATTN/DRONE reads done everywhere; now safe to overwrite with HDT
        if (lane == 0) {
            float s0v = g_s0[0];
            #pragma unroll
            for (int i = 0; i < 4; i++) sm[OFF_T + w * 4 + i] = pt[i] + s0v;
        }
        *(float4*)&sm[OFF_HDT + (k4 + 0) * HDTLD + w * 4] = make_float4(ho[0].x, ho[1].x, ho[2].x, ho[3].x);
        *(float4*)&sm[OFF_HDT + (k4 + 1) * HDTLD + w * 4] = make_float4(ho[0].y, ho[1].y, ho[2].y, ho[3].y);
        *(float4*)&sm[OFF_HDT + (k4 + 2) * HDTLD + w * 4] = make_float4(ho[0].z, ho[1].z, ho[2].z, ho[3].z);
        *(float4*)&sm[OFF_HDT + (k4 + 3) * HDTLD + w * 4] = make_float4(ho[0].w, ho[1].w, ho[2].w, ho[3].w);
    }
    __syncthreads();

    // ---- 5. h_dock (FFMA2, wbar from gmem): tile 8m x 4k -> hkT[k][m] ----
    {
        const int m0 = (t & 7) * 8, k0 = (t >> 3) * 4;
        u64 acc2[8][2] = {};
        #pragma unroll
        for (int f = 0; f < 16; f++) {
            ulonglong2 wv = *(const ulonglong2*)&g_wbar[f * 128 + k0];
            float4 da = *(float4*)&sm[OFF_DOCKT + f * DKTLD + m0];
            float4 db = *(float4*)&sm[OFF_DOCKT + f * DKTLD + m0 + 4];
            u64 d0 = pk2(da.x, da.x), d1 = pk2(da.y, da.y), d2 = pk2(da.z, da.z), d3 = pk2(da.w, da.w);
            u64 d4 = pk2(db.x, db.x), d5 = pk2(db.y, db.y), d6 = pk2(db.z, db.z), d7 = pk2(db.w, db.w);
            fma2(acc2[0][0], d0, wv.x); fma2(acc2[0][1], d0, wv.y);
            fma2(acc2[1][0], d1, wv.x); fma2(acc2[1][1], d1, wv.y);
            fma2(acc2[2][0], d2, wv.x); fma2(acc2[2][1], d2, wv.y);
            fma2(acc2[3][0], d3, wv.x); fma2(acc2[3][1], d3, wv.y);
            fma2(acc2[4][0], d4, wv.x); fma2(acc2[4][1], d4, wv.y);
            fma2(acc2[5][0], d5, wv.x); fma2(acc2[5][1], d5, wv.y);
            fma2(acc2[6][0], d6, wv.x); fma2(acc2[6][1], d6, wv.y);
            fma2(acc2[7][0], d7, wv.x); fma2(acc2[7][1], d7, wv.y);
        }
        float accf[8][4];
        #pragma unroll
        for (int m = 0; m < 8; m++) {
            float2 a = up2(acc2[m][0]), bq = up2(acc2[m][1]);
            accf[m][0] = a.x; accf[m][1] = a.y; accf[m][2] = bq.x; accf[m][3] = bq.y;
        }
        #pragma unroll
        for (int q = 0; q < 4; q++) {
            float4 va = make_float4(eluf(accf[0][q]), eluf(accf[1][q]), eluf(accf[2][q]), eluf(accf[3][q]));
            float4 vb4 = make_float4(eluf(accf[4][q]), eluf(accf[5][q]), eluf(accf[6][q]), eluf(accf[7][q]));
            *(float4*)&sm[OFF_HKT + (k0 + q) * HKTLD + m0] = va;
            *(float4*)&sm[OFF_HKT + (k0 + q) * HKTLD + m0 + 4] = vb4;
        }
    }
    __syncthreads();

    // ---- 6. r = hd @ M + vb (FFMA2, M from gmem/L2): tile 2n x 8j -> rT[j][n] ----
    {
        const int n0 = (t & 15) * 2, j0 = (t >> 4) * 8;
        u64 acc2[2][4] = {};
        #pragma unroll 8
        for (int al = 0; al < 128; al++) {
            ulonglong2 m01 = *(const ulonglong2*)&g_M[al * 128 + j0];
            ulonglong2 m23 = *(const ulonglong2*)&g_M[al * 128 + j0 + 4];
            float2 hv = *(float2*)&sm[OFF_HDT + al * HDTLD + n0];
            u64 h0 = pk2(hv.x, hv.x), h1 = pk2(hv.y, hv.y);
            fma2(acc2[0][0], h0, m01.x); fma2(acc2[0][1], h0, m01.y);
            fma2(acc2[0][2], h0, m23.x); fma2(acc2[0][3], h0, m23.y);
            fma2(acc2[1][0], h1, m01.x); fma2(acc2[1][1], h1, m01.y);
            fma2(acc2[1][2], h1, m23.x); fma2(acc2[1][3], h1, m23.y);
        }
        #pragma unroll
        for (int jp = 0; jp < 4; jp++) {
            float2 a0 = up2(acc2[0][jp]);
            float2 a1 = up2(acc2[1][jp]);
            float vb0 = sm[OFF_VB + j0 + 2 * jp], vb1 = sm[OFF_VB + j0 + 2 * jp + 1];
            *(float2*)&sm[OFF_RT + (j0 + 2 * jp) * RTLD + n0]     = make_float2(a0.x + vb0, a1.x + vb0);
            *(float2*)&sm[OFF_RT + (j0 + 2 * jp + 1) * RTLD + n0] = make_float2(a0.y + vb1, a1.y + vb1);
        }
    }
    __syncthreads();

    // ---- 7. logits (FFMA2): tile 2n x 4m, adj from gmem ----
    {
        const int n0 = (t >> 4) * 2, m0 = (t & 15) * 4;
        const float* adjp = rowp + 1536;
        float4 j0v = *(const float4*)&adjp[n0 * 64 + m0];
        float4 j1v = *(const float4*)&adjp[(n0 + 1) * 64 + m0];
        u64 acc2[2][2] = {};
        #pragma unroll 4
        for (int j = 0; j < 128; j++) {
            float2 rv = *(float2*)&sm[OFF_RT + j * RTLD + n0];
            ulonglong2 hv = *(ulonglong2*)&sm[OFF_HKT + j * HKTLD + m0];
            u64 r0 = pk2(rv.x, rv.x), r1 = pk2(rv.y, rv.y);
            fma2(acc2[0][0], r0, hv.x); fma2(acc2[0][1], r0, hv.y);
            fma2(acc2[1][0], r1, hv.x); fma2(acc2[1][1], r1, hv.y);
        }
        float2 p00 = up2(acc2[0][0]), p01 = up2(acc2[0][1]);
        float2 p10 = up2(acc2[1][0]), p11 = up2(acc2[1][1]);
        float t0 = sm[OFF_T + n0], t1 = sm[OFF_T + n0 + 1];
        float4 o0, o1;
        o0.x = j0v.x > 0.f ? p00.x + t0 : NEGV; o0.y = j0v.y > 0.f ? p00.y + t0 : NEGV;
        o0.z = j0v.z > 0.f ? p01.x + t0 : NEGV; o0.w = j0v.w > 0.f ? p01.y + t0 : NEGV;
        o1.x = j1v.x > 0.f ? p10.x + t1 : NEGV; o1.y = j1v.y > 0.f ? p10.y + t1 : NEGV;
        o1.z = j1v.z > 0.f ? p11.x + t1 : NEGV; o1.w = j1v.w > 0.f ? p11.y + t1 : NEGV;
        float* op = out_logits + (size_t)b * 2048;
        *(float4*)&op[n0 * 64 + m0] = o0;
        *(float4*)&op[(n0 + 1) * 64 + m0] = o1;
    }
}

// ================= critic: split-K(8) GEMM then combine =================
__global__ void __launch_bounds__(256) critic_gemm(const float* __restrict__ Wc1)
{
    __shared__ float s_chunk[32 * 128];
    const int t = threadIdx.x;
    const int b0 = blockIdx.x * 32;
    const int kb = blockIdx.y * 512;
    const int j = t & 63, rg = t >> 6;
    float acc[8] = {};

    for (int c = 0; c < 4; c++) {
        const int kbase = kb + c * 128;
        __syncthreads();
        for (int idx = t; idx < 1024; idx += 256) {
            int r = idx >> 5, c4 = (idx & 31) * 4;
            *(float4*)&s_chunk[r * 128 + c4] =
                *(const float4*)&g_hd[(size_t)(b0 + r) * 4096 + kbase + c4];
        }
        __syncthreads();
        for (int ii = 0; ii < 128; ii += 4) {
            float w0 = Wc1[(size_t)(kbase + ii    ) * 64 + j];
            float w1 = Wc1[(size_t)(kbase + ii + 1) * 64 + j];
            float w2 = Wc1[(size_t)(kbase + ii + 2) * 64 + j];
            float w3 = Wc1[(size_t)(kbase + ii + 3) * 64 + j];
            #pragma unroll
            for (int r = 0; r < 8; r++) {
                float4 h4 = *(const float4*)&s_chunk[(rg * 8 + r) * 128 + ii];
                acc[r] += h4.x * w0 + h4.y * w1 + h4.z * w2 + h4.w * w3;
            }
        }
    }
    #pragma unroll
    for (int r = 0; r < 8; r++)
        g_hpart[((size_t)blockIdx.y * NB + b0 + rg * 8 + r) * 64 + j] = acc[r];
}

__global__ void __launch_bounds__(256) critic_final(
    const float* __restrict__ bc1, const float* __restrict__ Wc2,
    const float* __restrict__ bc2, float* __restrict__ out_values)
{
    const int w = threadIdx.x >> 5, lane = threadIdx.x & 31;
    const int b = blockIdx.x * 8 + w;
    float a = 0.f;
    #pragma unroll
    for (int half = 0; half < 2; half++) {
        int jj = lane + 32 * half;
        size_t o = (size_t)b * 64 + jj;
        float h = bc1[jj];
        #pragma unroll
        for (int p = 0; p < 8; p++) h += g_hpart[(size_t)p * NB * 64 + o];
        a += (h > 0.f ? h : 0.f) * Wc2[jj];
    }
    #pragma unroll
    for (int o = 16; o; o >>= 1) a += __shfl_xor_sync(~0u, a, o);
    if (lane == 0) out_values[b] = a + bc2[0];
}

extern "C" void kernel_launch(void* const* d_in, const int* in_sizes, int n_in,
                              void* d_out, int out_size)
{
    const float* obs  = (const float*)d_in[0];
    const float* Wdr  = (const float*)d_in[1];
    const float* Wdk  = (const float*)d_in[2];
    const float* asrc = (const float*)d_in[3];
    const float* adst = (const float*)d_in[4];
    const float* Wc1  = (const float*)d_in[5];
    const float* bc1  = (const float*)d_in[6];
    const float* Wc2  = (const float*)d_in[7];
    const float* bc2  = (const float*)d_in[8];
    const float* Wad  = (const float*)d_in[9];
    const float* bad  = (const float*)d_in[10];
    const float* Wak  = (const float*)d_in[11];
    const float* bak  = (const float*)d_in[12];

    float* out        = (float*)d_out;
    float* out_values = out;
    float* out_logits = out + NB;

    cudaFuncSetAttribute(gat_main, cudaFuncAttributeMaxDynamicSharedMemorySize,
                         SMF * (int)sizeof(float));

    precomp<<<17, 256>>>(Wdr, Wdk, asrc, adst, Wad, Wak, bad, bak);
    gat_main<<<NB, 256, SMF * sizeof(float)>>>(obs, Wdk, out_logits);
    critic_gemm<<<dim3(NB / 32, 8), 256>>>(Wc1);
    critic_final<<<NB / 8, 256>>>(bc1, Wc2, bc2, out_values);
}

// round 8
// speedup vs baseline: 1.4479x; 1.0925x over previous
#include <cuda_runtime.h>

#define NB 4096
#define ND 32
#define NK 64
#define NHID 128
#define ALPHA 0.2f
#define NEGV (-9e15f)
#define OBSW 3584

// ---- gat_main smem layout (float offsets), phase-lifetime aliased ----
// timeline: load -> src/dst -> attn -> h_drone -> r-GEMM -> h_dock -> logits
#define OFF_ADJ   0        // 2048  dead after attn
#define OFF_CT    2048     // 2112  dead after h_drone
#define CTLD 132
#define OFF_RT    0        // 4096  written in r-GEMM (over ADJ+CT)
#define RTLD 32
#define OFF_DOCKT 4160     // 1088  live until h_dock
#define DKTLD 68
#define OFF_HDT   5248     // 4608  dead after r-GEMM
#define HDTLD 36
#define OFF_HKT   5248     // 8192  written in h_dock (over HDT)
#define HKTLD 64
// early scratch aliased into upper HKT region (untouched until h_dock)
#define OFF_SRC   9856     // 128
#define OFF_DST   9984     // 256
#define OFF_VS    10240    // 64
#define OFF_VD    10304    // 64
#define OFF_ATTN  10368    // 1024 (128 per warp: 2 rows)
#define OFF_DRONE 11392    // 512
// persistent tail
#define OFF_U     13440    // 128
#define OFF_VB    13568    // 128
#define OFF_T     13696    // 32
#define SMF       13728    // 54912 B -> 4 CTAs/SM

typedef unsigned long long u64;

__device__ __forceinline__ u64 pk2(float lo, float hi) {
    u64 r; asm("mov.b64 %0,{%1,%2};" : "=l"(r) : "f"(lo), "f"(hi)); return r;
}
__device__ __forceinline__ void fma2(u64& d, u64 a, u64 b) {
    asm("fma.rn.f32x2 %0, %1, %2, %0;" : "+l"(d) : "l"(a), "l"(b));
}
__device__ __forceinline__ float2 up2(u64 v) {
    float2 f; asm("mov.b64 {%0,%1},%2;" : "=f"(f.x), "=f"(f.y) : "l"(v)); return f;
}

__device__ float g_hd[(size_t)NB * ND * NHID];   // 64 MB
__device__ float g_hpart[8ull * NB * 64];        // 8 MB critic partials
__device__ float g_M[NHID * NHID];
__device__ float g_vb[NHID];
__device__ float g_u[NHID];
__device__ float g_s0[1];
__device__ float g_vsrc[64];
__device__ float g_vdst[64];
__device__ float g_wbar[16 * NHID];

__device__ __forceinline__ float eluf(float x) { return x > 0.f ? x : expm1f(x); }

// ================= precompute (batch-independent), grid=17 =================
__global__ void precomp(const float* __restrict__ Wdr, const float* __restrict__ Wdk,
                        const float* __restrict__ asrc, const float* __restrict__ adst,
                        const float* __restrict__ Wad, const float* __restrict__ Wak,
                        const float* __restrict__ bad, const float* __restrict__ bak)
{
    const int t = threadIdx.x;
    if (blockIdx.x < 16) {
        __shared__ float swad[8 * 128];
        __shared__ float swak[32 * 128];
        const int a0 = blockIdx.x * 8;
        for (int i = t; i < 1024; i += 256) swad[i] = Wad[a0 * 128 + i];
        for (int jb = 0; jb < 4; jb++) {
            __syncthreads();
            for (int i = t; i < 4096; i += 256) swak[i] = Wak[jb * 4096 + i];
            __syncthreads();
            const int aa = t >> 5, jl = t & 31;
            float s = 0.f;
            for (int c = 0; c < 128; c++) {
                int cc = (c + jl) & 127;
                s += swad[aa * 128 + cc] * swak[jl * 128 + cc];
            }
            g_M[(a0 + aa) * 128 + jb * 32 + jl] = s;
        }
        if (t < 8) {
            float s = 0.f;
            for (int c = 0; c < 128; c++) s += swad[t * 128 + c] * bak[c];
            g_u[a0 + t] = s;
        }
    } else {
        __shared__ float sb[128];
        if (t < 128) sb[t] = bad[t];
        __syncthreads();
        if (t < 128) {
            float s = 0.f;
            for (int c = 0; c < 128; c++) s += sb[c] * Wak[t * 128 + c];
            g_vb[t] = s;
        }
        if (t == 0) {
            float s = 0.f;
            for (int c = 0; c < 128; c++) s += sb[c] * bak[c];
            g_s0[0] = s;
        }
        if (t < 64) {
            int h = t >> 4, f = t & 15;
            float s = 0.f;
            for (int c = 0; c < 128; c++) s += Wdr[(h * 16 + f) * 128 + c] * asrc[h * 128 + c];
            g_vsrc[t] = s;
        } else if (t < 128) {
            int u2 = t - 64, h = u2 >> 4, f = u2 & 15;
            float s = 0.f;
            for (int c = 0; c < 128; c++) s += Wdk[(h * 16 + f) * 128 + c] * adst[h * 128 + c];
            g_vdst[u2] = s;
        }
        for (int i = t; i < 2048; i += 256) {
            float s = Wdk[i] + Wdk[2048 + i] + Wdk[4096 + i] + Wdk[6144 + i];
            g_wbar[i] = s * 0.25f;
        }
    }
}

// ================= per-batch kernel =================
__global__ void __launch_bounds__(256, 4) gat_main(
    const float* __restrict__ obs, const float* __restrict__ Wdk,
    float* __restrict__ out_logits)
{
    extern __shared__ float sm[];
    const int b = blockIdx.x, t = threadIdx.x;
    const int w = t >> 5, lane = t & 31;
    const int k4 = lane * 4;
    const float* rowp = obs + (size_t)b * OBSW;

    // ---- 1. load per-batch data ----
    for (int i = t; i < 512;  i += 256) sm[OFF_DRONE + i] = rowp[i];
    for (int i = t; i < 1024; i += 256) {
        int m = i >> 4, f = i & 15;
        sm[OFF_DOCKT + f * DKTLD + m] = rowp[512 + i];
    }
    for (int i = t; i < 2048; i += 256) sm[OFF_ADJ + i] = rowp[1536 + i];
    if (t < 64)       sm[OFF_VS + t]       = g_vsrc[t];
    else if (t < 128) sm[OFF_VD + t - 64]  = g_vdst[t - 64];
    else              sm[OFF_VB + t - 128] = g_vb[t - 128];
    for (int i = t; i < 128; i += 256) sm[OFF_U + i] = g_u[i];
    __syncthreads();

    // ---- 2. src[h,n], dst[h,m] ----
    if (t < 128) {
        int h = t >> 5, n = t & 31;
        float s = 0.f;
        #pragma unroll
        for (int f = 0; f < 16; f++) s += sm[OFF_DRONE + n * 16 + f] * sm[OFF_VS + h * 16 + f];
        sm[OFF_SRC + t] = s;
    }
    {
        int h = t >> 6, m = t & 63;
        float s = 0.f;
        #pragma unroll
        for (int f = 0; f < 16; f++) s += sm[OFF_DOCKT + f * DKTLD + m] * sm[OFF_VD + h * 16 + f];
        sm[OFF_DST + h * 64 + m] = s;
    }
    __syncthreads();

    // ---- 3. attention: paired rows, softmax + cT[f][r] ----
    {
        const int h = w >> 1;                   // warp w owns rows w*16..w*16+15, all in head h
        const int fl = lane & 15, mb = (lane >> 4) * 32;
        const float d0 = sm[OFF_DST + h * 64 + lane];
        const float d1 = sm[OFF_DST + h * 64 + 32 + lane];
        for (int rp = 0; rp < 8; rp++) {
            const int r0 = w * 16 + rp * 2, r1 = r0 + 1;
            const int n0 = r0 & 31, n1 = r1 & 31;
            float sc0 = sm[OFF_SRC + h * 32 + n0];
            float sc1 = sm[OFF_SRC + h * 32 + n1];
            float e00 = sc0 + d0, e01 = sc0 + d1, e10 = sc1 + d0, e11 = sc1 + d1;
            e00 = e00 > 0.f ? e00 : ALPHA * e00;
            e01 = e01 > 0.f ? e01 : ALPHA * e01;
            e10 = e10 > 0.f ? e10 : ALPHA * e10;
            e11 = e11 > 0.f ? e11 : ALPHA * e11;
            if (!(sm[OFF_ADJ + n0 * 64 + lane] > 0.f))      e00 = NEGV;
            if (!(sm[OFF_ADJ + n0 * 64 + 32 + lane] > 0.f)) e01 = NEGV;
            if (!(sm[OFF_ADJ + n1 * 64 + lane] > 0.f))      e10 = NEGV;
            if (!(sm[OFF_ADJ + n1 * 64 + 32 + lane] > 0.f)) e11 = NEGV;
            float mx0 = fmaxf(e00, e01), mx1 = fmaxf(e10, e11);
            #pragma unroll
            for (int o = 16; o; o >>= 1) {
                mx0 = fmaxf(mx0, __shfl_xor_sync(~0u, mx0, o));
                mx1 = fmaxf(mx1, __shfl_xor_sync(~0u, mx1, o));
            }
            float p00 = __expf(e00 - mx0), p01 = __expf(e01 - mx0);
            float p10 = __expf(e10 - mx1), p11 = __expf(e11 - mx1);
            float su0 = p00 + p01, su1 = p10 + p11;
            #pragma unroll
            for (int o = 16; o; o >>= 1) {
                su0 += __shfl_xor_sync(~0u, su0, o);
                su1 += __shfl_xor_sync(~0u, su1, o);
            }
            float iv0 = 1.0f / su0, iv1 = 1.0f / su1;
            sm[OFF_ATTN + w * 128 + lane]       = p00 * iv0;
            sm[OFF_ATTN + w * 128 + 32 + lane]  = p01 * iv0;
            sm[OFF_ATTN + w * 128 + 64 + lane]  = p10 * iv1;
            sm[OFF_ATTN + w * 128 + 96 + lane]  = p11 * iv1;
            __syncwarp();
            float cc0 = 0.f, cc1 = 0.f;
            #pragma unroll
            for (int mm = 0; mm < 32; mm += 4) {
                float4 dv  = *(float4*)&sm[OFF_DOCKT + fl * DKTLD + mb + mm];
                float4 av0 = *(float4*)&sm[OFF_ATTN + w * 128 + mb + mm];
                float4 av1 = *(float4*)&sm[OFF_ATTN + w * 128 + 64 + mb + mm];
                cc0 += av0.x * dv.x + av0.y * dv.y + av0.z * dv.z + av0.w * dv.w;
                cc1 += av1.x * dv.x + av1.y * dv.y + av1.z * dv.z + av1.w * dv.w;
            }
            cc0 += __shfl_xor_sync(~0u, cc0, 16);
            cc1 += __shfl_xor_sync(~0u, cc1, 16);
            if (lane < 16) {
                sm[OFF_CT + fl * CTLD + r0] = cc0;
                sm[OFF_CT + fl * CTLD + r1] = cc1;
            }
            __syncwarp();
        }
    }
    __syncthreads();

    // ---- 4. h_drone (FFMA2, Wdk from gmem): warp w owns n=w*4..+3, lane owns k4 ----
    u64 hacc2[8] = {};
    #pragma unroll 4
    for (int hf = 0; hf < 64; hf++) {
        ulonglong2 wv = *(const ulonglong2*)&Wdk[hf * 128 + k4];
        float4 cv = *(float4*)&sm[OFF_CT + (hf & 15) * CTLD + (hf >> 4) * 32 + w * 4];
        u64 c0 = pk2(cv.x, cv.x), c1 = pk2(cv.y, cv.y);
        u64 c2 = pk2(cv.z, cv.z), c3 = pk2(cv.w, cv.w);
        fma2(hacc2[0], c0, wv.x); fma2(hacc2[1], c0, wv.y);
        fma2(hacc2[2], c1, wv.x); fma2(hacc2[3], c1, wv.y);
        fma2(hacc2[4], c2, wv.x); fma2(hacc2[5], c2, wv.y);
        fma2(hacc2[6], c3, wv.x); fma2(hacc2[7], c3, wv.y);
    }
    {
        float4 ho[4];
        #pragma unroll
        for (int i = 0; i < 4; i++) {
            float2 lo = up2(hacc2[2 * i]), hi = up2(hacc2[2 * i + 1]);
            ho[i].x = eluf(lo.x * 0.25f); ho[i].y = eluf(lo.y * 0.25f);
            ho[i].z = eluf(hi.x * 0.25f); ho[i].w = eluf(hi.y * 0.25f);
            *(float4*)&g_hd[((size_t)b * ND + w * 4 + i) * 128 + k4] = ho[i];
        }
        // t[n] = hd[n,:].u + s0 via warp reduce
        float4 u4 = *(float4*)&sm[OFF_U + k4];
        float pt[4];
        #pragma unroll
        for (int i = 0; i < 4; i++)
            pt[i] = ho[i].x * u4.x + ho[i].y * u4.y + ho[i].z * u4.z + ho[i].w * u4.w;
        #pragma unroll
        for (int i = 0; i < 4; i++)
            #pragma unroll
            for (int o = 16; o; o >>= 1) pt[i] += __shfl_xor_sync(~0u, pt[i], o);
        if (lane == 0) {
            float s0v = g_s0[0];
            #pragma unroll
            for (int i = 0; i < 4; i++) sm[OFF_T + w * 4 + i] = pt[i] + s0v;
        }
        *(float4*)&sm[OFF_HDT + (k4 + 0) * HDTLD + w * 4] = make_float4(ho[0].x, ho[1].x, ho[2].x, ho[3].x);
        *(float4*)&sm[OFF_HDT + (k4 + 1) * HDTLD + w * 4] = make_float4(ho[0].y, ho[1].y, ho[2].y, ho[3].y);
        *(float4*)&sm[OFF_HDT + (k4 + 2) * HDTLD + w * 4] = make_float4(ho[0].z, ho[1].z, ho[2].z, ho[3].z);
        *(float4*)&sm[OFF_HDT + (k4 + 3) * HDTLD + w * 4] = make_float4(ho[0].w, ho[1].w, ho[2].w, ho[3].w);
    }
    __syncthreads();

    // ---- 5. r = hd @ M + vb (FFMA2, M from gmem/L2): tile 2n x 8j -> rT[j][n] ----
    {
        const int n0 = (t & 15) * 2, j0 = (t >> 4) * 8;
        u64 acc2[2][4] = {};
        #pragma unroll 8
        for (int al = 0; al < 128; al++) {
            ulonglong2 m01 = *(const ulonglong2*)&g_M[al * 128 + j0];
            ulonglong2 m23 = *(const ulonglong2*)&g_M[al * 128 + j0 + 4];
            float2 hv = *(float2*)&sm[OFF_HDT + al * HDTLD + n0];
            u64 h0 = pk2(hv.x, hv.x), h1 = pk2(hv.y, hv.y);
            fma2(acc2[0][0], h0, m01.x); fma2(acc2[0][1], h0, m01.y);
            fma2(acc2[0][2], h0, m23.x); fma2(acc2[0][3], h0, m23.y);
            fma2(acc2[1][0], h1, m01.x); fma2(acc2[1][1], h1, m01.y);
            fma2(acc2[1][2], h1, m23.x); fma2(acc2[1][3], h1, m23.y);
        }
        __syncthreads();   // HDT reads done everywhere; RT region (over ADJ/CT) now writable
        #pragma unroll
        for (int jp = 0; jp < 4; jp++) {
            float2 a0 = up2(acc2[0][jp]);
            float2 a1 = up2(acc2[1][jp]);
            float vb0 = sm[OFF_VB + j0 + 2 * jp], vb1 = sm[OFF_VB + j0 + 2 * jp + 1];
            *(float2*)&sm[OFF_RT + (j0 + 2 * jp) * RTLD + n0]     = make_float2(a0.x + vb0, a1.x + vb0);
            *(float2*)&sm[OFF_RT + (j0 + 2 * jp + 1) * RTLD + n0] = make_float2(a0.y + vb1, a1.y + vb1);
        }
    }
    __syncthreads();

    // ---- 6. h_dock (FFMA2, wbar from gmem): tile 8m x 4k -> hkT[k][m] (over HDT) ----
    {
        const int m0 = (t & 7) * 8, k0 = (t >> 3) * 4;
        u64 acc2[8][2] = {};
        #pragma unroll
        for (int f = 0; f < 16; f++) {
            ulonglong2 wv = *(const ulonglong2*)&g_wbar[f * 128 + k0];
            float4 da = *(float4*)&sm[OFF_DOCKT + f * DKTLD + m0];
            float4 db = *(float4*)&sm[OFF_DOCKT + f * DKTLD + m0 + 4];
            u64 d0 = pk2(da.x, da.x), d1 = pk2(da.y, da.y), d2 = pk2(da.z, da.z), d3 = pk2(da.w, da.w);
            u64 d4 = pk2(db.x, db.x), d5 = pk2(db.y, db.y), d6 = pk2(db.z, db.z), d7 = pk2(db.w, db.w);
            fma2(acc2[0][0], d0, wv.x); fma2(acc2[0][1], d0, wv.y);
            fma2(acc2[1][0], d1, wv.x); fma2(acc2[1][1], d1, wv.y);
            fma2(acc2[2][0], d2, wv.x); fma2(acc2[2][1], d2, wv.y);
            fma2(acc2[3][0], d3, wv.x); fma2(acc2[3][1], d3, wv.y);
            fma2(acc2[4][0], d4, wv.x); fma2(acc2[4][1], d4, wv.y);
            fma2(acc2[5][0], d5, wv.x); fma2(acc2[5][1], d5, wv.y);
            fma2(acc2[6][0], d6, wv.x); fma2(acc2[6][1], d6, wv.y);
            fma2(acc2[7][0], d7, wv.x); fma2(acc2[7][1], d7, wv.y);
        }
        float accf[8][4];
        #pragma unroll
        for (int m = 0; m < 8; m++) {
            float2 a = up2(acc2[m][0]), bq = up2(acc2[m][1]);
            accf[m][0] = a.x; accf[m][1] = a.y; accf[m][2] = bq.x; accf[m][3] = bq.y;
        }
        #pragma unroll
        for (int q = 0; q < 4; q++) {
            float4 va = make_float4(eluf(accf[0][q]), eluf(accf[1][q]), eluf(accf[2][q]), eluf(accf[3][q]));
            float4 vb4 = make_float4(eluf(accf[4][q]), eluf(accf[5][q]), eluf(accf[6][q]), eluf(accf[7][q]));
            *(float4*)&sm[OFF_HKT + (k0 + q) * HKTLD + m0] = va;
            *(float4*)&sm[OFF_HKT + (k0 + q) * HKTLD + m0 + 4] = vb4;
        }
    }
    __syncthreads();

    // ---- 7. logits (FFMA2): tile 2n x 4m, adj from gmem ----
    {
        const int n0 = (t >> 4) * 2, m0 = (t & 15) * 4;
        const float* adjp = rowp + 1536;
        float4 j0v = *(const float4*)&adjp[n0 * 64 + m0];
        float4 j1v = *(const float4*)&adjp[(n0 + 1) * 64 + m0];
        u64 acc2[2][2] = {};
        #pragma unroll 4
        for (int j = 0; j < 128; j++) {
            float2 rv = *(float2*)&sm[OFF_RT + j * RTLD + n0];
            ulonglong2 hv = *(ulonglong2*)&sm[OFF_HKT + j * HKTLD + m0];
            u64 r0 = pk2(rv.x, rv.x), r1 = pk2(rv.y, rv.y);
            fma2(acc2[0][0], r0, hv.x); fma2(acc2[0][1], r0, hv.y);
            fma2(acc2[1][0], r1, hv.x); fma2(acc2[1][1], r1, hv.y);
        }
        float2 p00 = up2(acc2[0][0]), p01 = up2(acc2[0][1]);
        float2 p10 = up2(acc2[1][0]), p11 = up2(acc2[1][1]);
        float t0 = sm[OFF_T + n0], t1 = sm[OFF_T + n0 + 1];
        float4 o0, o1;
        o0.x = j0v.x > 0.f ? p00.x + t0 : NEGV; o0.y = j0v.y > 0.f ? p00.y + t0 : NEGV;
        o0.z = j0v.z > 0.f ? p01.x + t0 : NEGV; o0.w = j0v.w > 0.f ? p01.y + t0 : NEGV;
        o1.x = j1v.x > 0.f ? p10.x + t1 : NEGV; o1.y = j1v.y > 0.f ? p10.y + t1 : NEGV;
        o1.z = j1v.z > 0.f ? p11.x + t1 : NEGV; o1.w = j1v.w > 0.f ? p11.y + t1 : NEGV;
        float* op = out_logits + (size_t)b * 2048;
        *(float4*)&op[n0 * 64 + m0] = o0;
        *(float4*)&op[(n0 + 1) * 64 + m0] = o1;
    }
}

// ================= critic: split-K(8) GEMM then combine =================
__global__ void __launch_bounds__(256) critic_gemm(const float* __restrict__ Wc1)
{
    __shared__ float s_chunk[32 * 128];
    const int t = threadIdx.x;
    const int b0 = blockIdx.x * 32;
    const int kb = blockIdx.y * 512;
    const int j = t & 63, rg = t >> 6;
    float acc[8] = {};

    for (int c = 0; c < 4; c++) {
        const int kbase = kb + c * 128;
        __syncthreads();
        for (int idx = t; idx < 1024; idx += 256) {
            int r = idx >> 5, c4 = (idx & 31) * 4;
            *(float4*)&s_chunk[r * 128 + c4] =
                *(const float4*)&g_hd[(size_t)(b0 + r) * 4096 + kbase + c4];
        }
        __syncthreads();
        for (int ii = 0; ii < 128; ii += 4) {
            float w0 = Wc1[(size_t)(kbase + ii    ) * 64 + j];
            float w1 = Wc1[(size_t)(kbase + ii + 1) * 64 + j];
            float w2 = Wc1[(size_t)(kbase + ii + 2) * 64 + j];
            float w3 = Wc1[(size_t)(kbase + ii + 3) * 64 + j];
            #pragma unroll
            for (int r = 0; r < 8; r++) {
                float4 h4 = *(const float4*)&s_chunk[(rg * 8 + r) * 128 + ii];
                acc[r] += h4.x * w0 + h4.y * w1 + h4.z * w2 + h4.w * w3;
            }
        }
    }
    #pragma unroll
    for (int r = 0; r < 8; r++)
        g_hpart[((size_t)blockIdx.y * NB + b0 + rg * 8 + r) * 64 + j] = acc[r];
}

__global__ void __launch_bounds__(256) critic_final(
    const float* __restrict__ bc1, const float* __restrict__ Wc2,
    const float* __restrict__ bc2, float* __restrict__ out_values)
{
    const int w = threadIdx.x >> 5, lane = threadIdx.x & 31;
    const int b = blockIdx.x * 8 + w;
    float a = 0.f;
    #pragma unroll
    for (int half = 0; half < 2; half++) {
        int jj = lane + 32 * half;
        size_t o = (size_t)b * 64 + jj;
        float h = bc1[jj];
        #pragma unroll
        for (int p = 0; p < 8; p++) h += g_hpart[(size_t)p * NB * 64 + o];
        a += (h > 0.f ? h : 0.f) * Wc2[jj];
    }
    #pragma unroll
    for (int o = 16; o; o >>= 1) a += __shfl_xor_sync(~0u, a, o);
    if (lane == 0) out_values[b] = a + bc2[0];
}

extern "C" void kernel_launch(void* const* d_in, const int* in_sizes, int n_in,
                              void* d_out, int out_size)
{
    const float* obs  = (const float*)d_in[0];
    const float* Wdr  = (const float*)d_in[1];
    const float* Wdk  = (const float*)d_in[2];
    const float* asrc = (const float*)d_in[3];
    const float* adst = (const float*)d_in[4];
    const float* Wc1  = (const float*)d_in[5];
    const float* bc1  = (const float*)d_in[6];
    const float* Wc2  = (const float*)d_in[7];
    const float* bc2  = (const float*)d_in[8];
    const float* Wad  = (const float*)d_in[9];
    const float* bad  = (const float*)d_in[10];
    const float* Wak  = (const float*)d_in[11];
    const float* bak  = (const float*)d_in[12];

    float* out        = (float*)d_out;
    float* out_values = out;
    float* out_logits = out + NB;

    cudaFuncSetAttribute(gat_main, cudaFuncAttributeMaxDynamicSharedMemorySize,
                         SMF * (int)sizeof(float));

    precomp<<<17, 256>>>(Wdr, Wdk, asrc, adst, Wad, Wak, bad, bak);
    gat_main<<<NB, 256, SMF * sizeof(float)>>>(obs, Wdk, out_logits);
    critic_gemm<<<dim3(NB / 32, 8), 256>>>(Wc1);
    critic_final<<<NB / 8, 256>>>(bc1, Wc2, bc2, out_values);
}